// round 5
// baseline (speedup 1.0000x reference)
#include <cuda_runtime.h>
#include <cuda_bf16.h>

// STFT: B=16, T=262144, n_fft=2048, hop=512, center reflect pad 1024.
// n_frames = 513, n_bins = 1025. Output [real(16,1025,513); imag(...)] fp32.
//
// Kernel A: 1024-pt complex FFT per frame (real packing), Stockham radices
//   8,8,4,4; stage 1 reads gmem; last stage fused with rfft unpack and stores
//   X directly (coalesced) to scratch in [b, f, k] float2 layout.
// Kernel B: tiled transpose scratch[b,f,k] -> real[b,k,f], imag[b,k,f].

#define NC        1024
#define ROWSTRIDE 1028
#define HOP       512
#define PADC      1024
#define T_LEN     262144
#define NFFT      2048
#define NFRAMES   513
#define NBINS     1025
#define NB        16
#define THREADS   512
#define FPB       4
#define NGRP      129
#define PI_F      3.14159265358979323846f
#define C4        0.70710678118654752f

#define PHY(i) ((i) ^ ((((unsigned)(i)) >> 3) & 15u))

// 67.3 MB scratch: [b][f][k] complex spectra before transpose
__device__ float2 g_scratch[(long)NB * NFRAMES * NBINS];

__device__ __forceinline__ float2 cadd(float2 a, float2 b) { return make_float2(a.x + b.x, a.y + b.y); }
__device__ __forceinline__ float2 csub(float2 a, float2 b) { return make_float2(a.x - b.x, a.y - b.y); }
__device__ __forceinline__ float2 cmulc(float2 a, float2 w) {
    return make_float2(a.x * w.x - a.y * w.y, a.x * w.y + a.y * w.x);
}

__device__ __forceinline__ void fft8(float2* a) {
    float2 e0 = cadd(a[0], a[4]), e1 = cadd(a[1], a[5]);
    float2 e2 = cadd(a[2], a[6]), e3 = cadd(a[3], a[7]);
    float2 o0 = csub(a[0], a[4]), o1 = csub(a[1], a[5]);
    float2 o2 = csub(a[2], a[6]), o3 = csub(a[3], a[7]);
    float2 ee0 = cadd(e0, e2), ee1 = cadd(e1, e3);
    float2 eo0 = csub(e0, e2), eo1 = csub(e1, e3);
    a[0] = cadd(ee0, ee1);
    a[4] = csub(ee0, ee1);
    a[2] = make_float2(eo0.x + eo1.y, eo0.y - eo1.x);
    a[6] = make_float2(eo0.x - eo1.y, eo0.y + eo1.x);
    float2 p1 = make_float2(C4 * (o1.x + o1.y), C4 * (o1.y - o1.x));
    float2 p2 = make_float2(o2.y, -o2.x);
    float2 p3 = make_float2(C4 * (o3.y - o3.x), -C4 * (o3.x + o3.y));
    float2 s0 = cadd(o0, p2), s1 = cadd(p1, p3);
    float2 d0 = csub(o0, p2), d1 = csub(p1, p3);
    a[1] = cadd(s0, s1);
    a[5] = csub(s0, s1);
    a[3] = make_float2(d0.x + d1.y, d0.y - d1.x);
    a[7] = make_float2(d0.x - d1.y, d0.y + d1.x);
}

__device__ __forceinline__ void fft4(float2& a0, float2& a1, float2& a2, float2& a3) {
    float2 t0 = cadd(a0, a2), t1 = csub(a0, a2);
    float2 t2 = cadd(a1, a3), t3 = csub(a1, a3);
    a0 = cadd(t0, t2);
    a2 = csub(t0, t2);
    float2 b1 = make_float2(t1.x + t3.y, t1.y - t3.x);
    float2 b3 = make_float2(t1.x - t3.y, t1.y + t3.x);
    a1 = b1;
    a3 = b3;
}

__device__ __forceinline__ void bar_frame(int fl) {
    asm volatile("bar.sync %0, 128;" :: "r"(fl + 1) : "memory");
}

__device__ __forceinline__ void unpack_pair(float2 zk, float2 zn, float cw, float sw,
                                            float2& Xk, float2& Xc) {
    const float er  = 0.5f * (zk.x + zn.x);
    const float ei  = 0.5f * (zk.y - zn.y);
    const float orr = 0.5f * (zk.y + zn.y);
    const float oi  = 0.5f * (zn.x - zk.x);
    const float pr  = orr * cw + oi * sw;
    const float pi2 = orr * sw - oi * cw;
    Xk = make_float2(er + pr,  ei - pi2);
    Xc = make_float2(er - pr, -ei - pi2);
}

__global__ __launch_bounds__(THREADS, 2)
void stft_fft_kernel(const float* __restrict__ x,
                     const float* __restrict__ win) {
    __shared__ float2 buf[FPB][ROWSTRIDE];

    const int g   = blockIdx.x % NGRP;
    const int b   = blockIdx.x / NGRP;
    const int tid = threadIdx.x;
    const int fl  = tid >> 7;
    const int u   = tid & 127;
    const int f   = g * FPB + fl;            // phantom if >= 513
    const float* __restrict__ xb = x + (long)b * T_LEN;
    const int base = f * HOP - PADC;

    float2 a[8];

    // ---- stage 1: radix-8, n=1024, s=1 — read gmem directly ----
    const bool interior = (base >= 0) && (base + NFFT <= T_LEN);
    if (interior) {
        const float2* __restrict__ xv = (const float2*)(xb + base);
        const float2* __restrict__ wv = (const float2*)win;
#pragma unroll
        for (int r = 0; r < 8; r++) {
            const int n = u + (r << 7);
            const float2 v = xv[n];
            const float2 w = wv[n];
            a[r] = make_float2(v.x * w.x, v.y * w.y);
        }
    } else {
#pragma unroll
        for (int r = 0; r < 8; r++) {
            const int n = u + (r << 7);
            int t0 = base + 2 * n;
            int t1 = base + 2 * n + 1;
            t0 = (t0 < 0) ? -t0 : ((t0 >= T_LEN) ? 2 * T_LEN - 2 - t0 : t0);
            t1 = (t1 < 0) ? -t1 : ((t1 >= T_LEN) ? 2 * T_LEN - 2 - t1 : t1);
            a[r] = make_float2(xb[t0] * win[2 * n], xb[t1] * win[2 * n + 1]);
        }
    }
    fft8(a);
    {
        float s1, c1;
        __sincosf((float)u * (-2.0f * PI_F / 1024.0f), &s1, &c1);
        const float2 w1 = make_float2(c1, s1);
        float2 wk = w1;
        a[1] = cmulc(a[1], wk);
#pragma unroll
        for (int r = 2; r < 8; r++) { wk = cmulc(wk, w1); a[r] = cmulc(a[r], wk); }
#pragma unroll
        for (int r = 0; r < 8; r++) buf[fl][PHY(8 * u + r)] = a[r];
    }
    bar_frame(fl);

    // ---- stage 2: radix-8, n=128, s=8 ----
#pragma unroll
    for (int r = 0; r < 8; r++) a[r] = buf[fl][PHY(u + (r << 7))];
    bar_frame(fl);
    fft8(a);
    {
        const int p = u >> 3;
        float s1, c1;
        __sincosf((float)p * (-2.0f * PI_F / 128.0f), &s1, &c1);
        const float2 w1 = make_float2(c1, s1);
        float2 wk = w1;
        a[1] = cmulc(a[1], wk);
#pragma unroll
        for (int r = 2; r < 8; r++) { wk = cmulc(wk, w1); a[r] = cmulc(a[r], wk); }
        const int dbase = u + 56 * p;
#pragma unroll
        for (int r = 0; r < 8; r++) buf[fl][PHY(dbase + 8 * r)] = a[r];
    }
    bar_frame(fl);

    // ---- stage 3: radix-4 x2, n=16, s=64 ----
    {
        float2 A4[2][4];
#pragma unroll
        for (int h = 0; h < 2; h++) {
            const int t = u + (h << 7);
#pragma unroll
            for (int r = 0; r < 4; r++) A4[h][r] = buf[fl][PHY(t + (r << 8))];
        }
        bar_frame(fl);
#pragma unroll
        for (int h = 0; h < 2; h++) {
            const int t = u + (h << 7);
            const int p = t >> 6;
            fft4(A4[h][0], A4[h][1], A4[h][2], A4[h][3]);
            float s1, c1;
            __sincosf((float)p * (-2.0f * PI_F / 16.0f), &s1, &c1);
            const float c2 = c1 * c1 - s1 * s1;
            const float s2 = 2.0f * c1 * s1;
            const float c3 = c1 * c2 - s1 * s2;
            const float s3 = c1 * s2 + s1 * c2;
            const int dbase = t + 192 * p;
            buf[fl][PHY(dbase)]       = A4[h][0];
            buf[fl][PHY(dbase + 64)]  = cmulc(A4[h][1], make_float2(c1, s1));
            buf[fl][PHY(dbase + 128)] = cmulc(A4[h][2], make_float2(c2, s2));
            buf[fl][PHY(dbase + 192)] = cmulc(A4[h][3], make_float2(c3, s3));
        }
        bar_frame(fl);
    }

    // ---- stage 4 (radix-4, trivial twiddles) fused with rfft unpack,
    //      store X directly to scratch [b][f][k] (coalesced runs of 32) ----
    {
        const int t1 = u;
        const int t2 = (u == 0) ? 128 : 256 - u;
        float2 z1[4], z2[4];
#pragma unroll
        for (int r = 0; r < 4; r++) {
            z1[r] = buf[fl][PHY(t1 + (r << 8))];
            z2[r] = buf[fl][PHY(t2 + (r << 8))];
        }
        fft4(z1[0], z1[1], z1[2], z1[3]);
        fft4(z2[0], z2[1], z2[2], z2[3]);

        if (f < NFRAMES) {
            float2* __restrict__ scrf = g_scratch + ((long)b * NFRAMES + f) * NBINS;
            if (u == 0) {
                scrf[0]    = make_float2(z1[0].x + z1[0].y, 0.0f);
                scrf[1024] = make_float2(z1[0].x - z1[0].y, 0.0f);
                scrf[512]  = make_float2(z1[2].x, -z1[2].y);
                float2 Xk, Xc;
                unpack_pair(z1[1], z1[3], C4, C4, Xk, Xc);
                scrf[256] = Xk; scrf[768] = Xc;
                unpack_pair(z2[0], z2[3], 0.92387953f, 0.38268343f, Xk, Xc);
                scrf[128] = Xk; scrf[896] = Xc;
                unpack_pair(z2[1], z2[2], 0.38268343f, 0.92387953f, Xk, Xc);
                scrf[384] = Xk; scrf[640] = Xc;
            } else {
                float ca, sa;
                __sincosf((float)u * (PI_F / 1024.0f), &sa, &ca);
                const float cp = C4 * (ca - sa);
                const float sp = C4 * (ca + sa);
                float2 Xk, Xc;
                unpack_pair(z1[0], z2[3], ca, sa, Xk, Xc);
                scrf[u] = Xk; scrf[1024 - u] = Xc;
                unpack_pair(z1[1], z2[2], cp, sp, Xk, Xc);
                scrf[u + 256] = Xk; scrf[768 - u] = Xc;
                unpack_pair(z1[2], z2[1], -sa, ca, Xk, Xc);
                scrf[u + 512] = Xk; scrf[512 - u] = Xc;
                unpack_pair(z1[3], z2[0], -sp, cp, Xk, Xc);
                scrf[u + 768] = Xk; scrf[256 - u] = Xc;
            }
        }
    }
}

// ---- Kernel B: transpose scratch[b,f,k] -> out real[b,k,f], imag[b,k,f] ----
#define TS 32
__global__ __launch_bounds__(256)
void transpose_kernel(float* __restrict__ out) {
    __shared__ float tr[TS][TS + 1];
    __shared__ float ti[TS][TS + 1];

    const int b  = blockIdx.z;
    const int f0 = blockIdx.y * TS;
    const int k0 = blockIdx.x * TS;
    const int tx = threadIdx.x;
    const int ty = threadIdx.y;     // 0..7

    const int k = k0 + tx;
#pragma unroll
    for (int j = 0; j < 4; j++) {
        const int fr = ty + 8 * j;          // row within tile
        const int f  = f0 + fr;
        if (f < NFRAMES && k < NBINS) {
            const float2 v = g_scratch[((long)b * NFRAMES + f) * NBINS + k];
            tr[fr][tx] = v.x;
            ti[fr][tx] = v.y;
        }
    }
    __syncthreads();

    const long imag_off = (long)NB * NBINS * NFRAMES;
    const int fo = f0 + tx;
#pragma unroll
    for (int j = 0; j < 4; j++) {
        const int kr = ty + 8 * j;
        const int ko = k0 + kr;
        if (ko < NBINS && fo < NFRAMES) {
            const long o = ((long)b * NBINS + ko) * NFRAMES + fo;
            out[o]            = tr[tx][kr];
            out[imag_off + o] = ti[tx][kr];
        }
    }
}

extern "C" void kernel_launch(void* const* d_in, const int* in_sizes, int n_in,
                              void* d_out, int out_size) {
    const float* x   = (const float*)d_in[0];
    const float* win = (const float*)d_in[1];
    float* out = (float*)d_out;
    stft_fft_kernel<<<NB * NGRP, THREADS>>>(x, win);
    dim3 tgrid((NBINS + TS - 1) / TS, (NFRAMES + TS - 1) / TS, NB);
    transpose_kernel<<<tgrid, dim3(32, 8)>>>(out);
}

// round 6
// speedup vs baseline: 1.3048x; 1.3048x over previous
#include <cuda_runtime.h>
#include <cuda_bf16.h>

// STFT: B=16, T=262144, n_fft=2048, hop=512, center reflect pad 1024.
// n_frames = 513, n_bins = 1025. Output [real(16,1025,513); imag(...)] fp32.
//
// Single kernel: 8 frames/CTA (512 thr, 64 thr/frame), 1024-pt complex FFT
// (real packing), Stockham radices 8,8,4,4; stage 1 reads gmem; final stage
// fused with rfft unpack writing X to smem; block-transposed store with
// full-sector (32B/frame-run) output writes. Dynamic smem 65.7KB, 2 CTA/SM.

#define NC        1024
#define SROW      1026      // float2 row stride: 2*SROW == 4 (mod 32) banks
#define HOP       512
#define PADC      1024
#define T_LEN     262144
#define NFFT      2048
#define NFRAMES   513
#define NBINS     1025
#define NB        16
#define THREADS   512
#define FPB       8
#define NGRP      65        // ceil(513/8)
#define PI_F      3.14159265358979323846f
#define C4        0.70710678118654752f

#define PHY(i) ((i) ^ ((((unsigned)(i)) >> 3) & 15u))

__device__ __forceinline__ float2 cadd(float2 a, float2 b) { return make_float2(a.x + b.x, a.y + b.y); }
__device__ __forceinline__ float2 csub(float2 a, float2 b) { return make_float2(a.x - b.x, a.y - b.y); }
__device__ __forceinline__ float2 cmulc(float2 a, float2 w) {
    return make_float2(a.x * w.x - a.y * w.y, a.x * w.y + a.y * w.x);
}

__device__ __forceinline__ void fft8(float2* a) {
    float2 e0 = cadd(a[0], a[4]), e1 = cadd(a[1], a[5]);
    float2 e2 = cadd(a[2], a[6]), e3 = cadd(a[3], a[7]);
    float2 o0 = csub(a[0], a[4]), o1 = csub(a[1], a[5]);
    float2 o2 = csub(a[2], a[6]), o3 = csub(a[3], a[7]);
    float2 ee0 = cadd(e0, e2), ee1 = cadd(e1, e3);
    float2 eo0 = csub(e0, e2), eo1 = csub(e1, e3);
    a[0] = cadd(ee0, ee1);
    a[4] = csub(ee0, ee1);
    a[2] = make_float2(eo0.x + eo1.y, eo0.y - eo1.x);
    a[6] = make_float2(eo0.x - eo1.y, eo0.y + eo1.x);
    float2 p1 = make_float2(C4 * (o1.x + o1.y), C4 * (o1.y - o1.x));
    float2 p2 = make_float2(o2.y, -o2.x);
    float2 p3 = make_float2(C4 * (o3.y - o3.x), -C4 * (o3.x + o3.y));
    float2 s0 = cadd(o0, p2), s1 = cadd(p1, p3);
    float2 d0 = csub(o0, p2), d1 = csub(p1, p3);
    a[1] = cadd(s0, s1);
    a[5] = csub(s0, s1);
    a[3] = make_float2(d0.x + d1.y, d0.y - d1.x);
    a[7] = make_float2(d0.x - d1.y, d0.y + d1.x);
}

__device__ __forceinline__ void fft4(float2& a0, float2& a1, float2& a2, float2& a3) {
    float2 t0 = cadd(a0, a2), t1 = csub(a0, a2);
    float2 t2 = cadd(a1, a3), t3 = csub(a1, a3);
    a0 = cadd(t0, t2);
    a2 = csub(t0, t2);
    float2 b1 = make_float2(t1.x + t3.y, t1.y - t3.x);
    float2 b3 = make_float2(t1.x - t3.y, t1.y + t3.x);
    a1 = b1;
    a3 = b3;
}

__device__ __forceinline__ void bar_frame(int fl) {
    asm volatile("bar.sync %0, 64;" :: "r"(fl + 1) : "memory");
}

__device__ __forceinline__ void unpack_pair(float2 zk, float2 zn, float cw, float sw,
                                            float2& Xk, float2& Xc) {
    const float er  = 0.5f * (zk.x + zn.x);
    const float ei  = 0.5f * (zk.y - zn.y);
    const float orr = 0.5f * (zk.y + zn.y);
    const float oi  = 0.5f * (zn.x - zk.x);
    const float pr  = orr * cw + oi * sw;
    const float pi2 = orr * sw - oi * cw;
    Xk = make_float2(er + pr,  ei - pi2);
    Xc = make_float2(er - pr, -ei - pi2);
}

extern __shared__ float2 buf[];   // FPB * SROW float2 = 65,664 B

__global__ __launch_bounds__(THREADS, 2)
void stft_kernel(const float* __restrict__ x,
                 const float* __restrict__ win,
                 float* __restrict__ out) {
    const int g   = blockIdx.x % NGRP;
    const int b   = blockIdx.x / NGRP;
    const int tid = threadIdx.x;
    const int fl  = tid >> 6;          // frame slot 0..7
    const int u   = tid & 63;          // lane within frame
    const int f   = g * FPB + fl;      // phantom if >= 513
    const float* __restrict__ xb = x + (long)b * T_LEN;
    const int base = f * HOP - PADC;
    float2* __restrict__ row = buf + fl * SROW;

    // ---- stage 1: radix-8, n=1024, s=1 — read gmem directly ----
    const bool interior = (base >= 0) && (base + NFFT <= T_LEN);
#pragma unroll
    for (int h = 0; h < 2; h++) {
        const int t = u + (h << 6);    // butterfly index 0..127
        float2 a[8];
        if (interior) {
            const float2* __restrict__ xv = (const float2*)(xb + base);
            const float2* __restrict__ wv = (const float2*)win;
#pragma unroll
            for (int r = 0; r < 8; r++) {
                const int n = t + (r << 7);
                const float2 v = xv[n];
                const float2 w = wv[n];
                a[r] = make_float2(v.x * w.x, v.y * w.y);
            }
        } else {
#pragma unroll
            for (int r = 0; r < 8; r++) {
                const int n = t + (r << 7);
                int t0 = base + 2 * n;
                int t1 = base + 2 * n + 1;
                t0 = (t0 < 0) ? -t0 : ((t0 >= T_LEN) ? 2 * T_LEN - 2 - t0 : t0);
                t1 = (t1 < 0) ? -t1 : ((t1 >= T_LEN) ? 2 * T_LEN - 2 - t1 : t1);
                a[r] = make_float2(xb[t0] * win[2 * n], xb[t1] * win[2 * n + 1]);
            }
        }
        fft8(a);
        float s1, c1;
        __sincosf((float)t * (-2.0f * PI_F / 1024.0f), &s1, &c1);
        const float2 w1 = make_float2(c1, s1);
        float2 wk = w1;
        a[1] = cmulc(a[1], wk);
#pragma unroll
        for (int r = 2; r < 8; r++) { wk = cmulc(wk, w1); a[r] = cmulc(a[r], wk); }
#pragma unroll
        for (int r = 0; r < 8; r++) row[PHY(8 * t + r)] = a[r];
    }
    bar_frame(fl);

    // ---- stage 2: radix-8, n=128, s=8 (read all, bar, compute+write) ----
    {
        float2 A[2][8];
#pragma unroll
        for (int h = 0; h < 2; h++) {
            const int t = u + (h << 6);
#pragma unroll
            for (int r = 0; r < 8; r++) A[h][r] = row[PHY(t + (r << 7))];
        }
        bar_frame(fl);
#pragma unroll
        for (int h = 0; h < 2; h++) {
            const int t = u + (h << 6);
            fft8(A[h]);
            const int p = t >> 3;
            float s1, c1;
            __sincosf((float)p * (-2.0f * PI_F / 128.0f), &s1, &c1);
            const float2 w1 = make_float2(c1, s1);
            float2 wk = w1;
            A[h][1] = cmulc(A[h][1], wk);
#pragma unroll
            for (int r = 2; r < 8; r++) { wk = cmulc(wk, w1); A[h][r] = cmulc(A[h][r], wk); }
            const int dbase = t + 56 * p;
#pragma unroll
            for (int r = 0; r < 8; r++) row[PHY(dbase + 8 * r)] = A[h][r];
        }
        bar_frame(fl);
    }

    // ---- stage 3: radix-4 x4, n=16, s=64 ----
    {
        float2 A4[4][4];
#pragma unroll
        for (int h = 0; h < 4; h++) {
            const int t = u + (h << 6);
#pragma unroll
            for (int r = 0; r < 4; r++) A4[h][r] = row[PHY(t + (r << 8))];
        }
        bar_frame(fl);
#pragma unroll
        for (int h = 0; h < 4; h++) {
            const int t = u + (h << 6);
            const int p = t >> 6;
            fft4(A4[h][0], A4[h][1], A4[h][2], A4[h][3]);
            float s1, c1;
            __sincosf((float)p * (-2.0f * PI_F / 16.0f), &s1, &c1);
            const float c2 = c1 * c1 - s1 * s1;
            const float s2 = 2.0f * c1 * s1;
            const float c3 = c1 * c2 - s1 * s2;
            const float s3 = c1 * s2 + s1 * c2;
            const int dbase = t + 192 * p;
            row[PHY(dbase)]       = A4[h][0];
            row[PHY(dbase + 64)]  = cmulc(A4[h][1], make_float2(c1, s1));
            row[PHY(dbase + 128)] = cmulc(A4[h][2], make_float2(c2, s2));
            row[PHY(dbase + 192)] = cmulc(A4[h][3], make_float2(c3, s3));
        }
        bar_frame(fl);
    }

    // ---- stage 4 (radix-4, trivial twiddles) fused with rfft unpack ----
    {
        float2 Z1[2][4], Z2[2][4];
#pragma unroll
        for (int h = 0; h < 2; h++) {
            const int ue = u + (h << 6);           // pair index 0..127
            const int t1 = ue;
            const int t2 = (ue == 0) ? 128 : 256 - ue;
#pragma unroll
            for (int r = 0; r < 4; r++) {
                Z1[h][r] = row[PHY(t1 + (r << 8))];
                Z2[h][r] = row[PHY(t2 + (r << 8))];
            }
        }
        bar_frame(fl);   // all reads done before X overwrites buf
#pragma unroll
        for (int h = 0; h < 2; h++) {
            const int ue = u + (h << 6);
            fft4(Z1[h][0], Z1[h][1], Z1[h][2], Z1[h][3]);
            fft4(Z2[h][0], Z2[h][1], Z2[h][2], Z2[h][3]);
            if (ue == 0) {
                row[0]    = make_float2(Z1[h][0].x + Z1[h][0].y, 0.0f);
                row[1024] = make_float2(Z1[h][0].x - Z1[h][0].y, 0.0f);
                row[512]  = make_float2(Z1[h][2].x, -Z1[h][2].y);
                float2 Xk, Xc;
                unpack_pair(Z1[h][1], Z1[h][3], C4, C4, Xk, Xc);
                row[256] = Xk; row[768] = Xc;
                unpack_pair(Z2[h][0], Z2[h][3], 0.92387953f, 0.38268343f, Xk, Xc);
                row[128] = Xk; row[896] = Xc;
                unpack_pair(Z2[h][1], Z2[h][2], 0.38268343f, 0.92387953f, Xk, Xc);
                row[384] = Xk; row[640] = Xc;
            } else {
                float ca, sa;
                __sincosf((float)ue * (PI_F / 1024.0f), &sa, &ca);
                const float cp = C4 * (ca - sa);
                const float sp = C4 * (ca + sa);
                float2 Xk, Xc;
                unpack_pair(Z1[h][0], Z2[h][3], ca, sa, Xk, Xc);
                row[ue] = Xk; row[1024 - ue] = Xc;
                unpack_pair(Z1[h][1], Z2[h][2], cp, sp, Xk, Xc);
                row[ue + 256] = Xk; row[768 - ue] = Xc;
                unpack_pair(Z1[h][2], Z2[h][1], -sa, ca, Xk, Xc);
                row[ue + 512] = Xk; row[512 - ue] = Xc;
                unpack_pair(Z1[h][3], Z2[h][0], -sp, cp, Xk, Xc);
                row[ue + 768] = Xk; row[256 - ue] = Xc;
            }
        }
    }
    __syncthreads();

    // ---- transposed store: lane j -> frame j&7, bin j>>3 (+64 per iter) ----
    // 8 consecutive f per k-row = 32B full-sector stores per plane.
    const int  fs     = tid & 7;
    const int  kb     = tid >> 3;         // 0..63
    const int  fstore = g * FPB + fs;
    const bool valid  = (fstore < NFRAMES);
    const long ro       = ((long)b * NBINS) * NFRAMES + fstore;
    const long imag_off = (long)NB * NBINS * NFRAMES;
    const float2* __restrict__ Xrow = buf + fs * SROW;
#pragma unroll
    for (int i = 0; i < 17; i++) {
        const int k = kb + (i << 6);
        if (k <= NC && valid) {
            const float2 X = Xrow[k];
            const long o = ro + (long)k * NFRAMES;
            out[o]            = X.x;
            out[imag_off + o] = X.y;
        }
    }
}

extern "C" void kernel_launch(void* const* d_in, const int* in_sizes, int n_in,
                              void* d_out, int out_size) {
    const float* x   = (const float*)d_in[0];
    const float* win = (const float*)d_in[1];
    float* out = (float*)d_out;
    const int smem_bytes = FPB * SROW * (int)sizeof(float2);   // 65,664
    cudaFuncSetAttribute(stft_kernel, cudaFuncAttributeMaxDynamicSharedMemorySize,
                         smem_bytes);
    stft_kernel<<<NB * NGRP, THREADS, smem_bytes>>>(x, win, out);
}